// round 10
// baseline (speedup 1.0000x reference)
#include <cuda_runtime.h>
#include <cuda_bf16.h>
#include <cstdint>

// ---------------------------------------------------------------------------
// B=8, TGT=256, SRC=512, D=1024, H=16, dh=64, TEMP=0.2
// Output: p_choose (8,16,256,512) then alpha (8,16,256,512), fp32.
// ---------------------------------------------------------------------------

#define D_DIM   1024
#define TGT     256
#define SRC     512
#define NB      8
#define NH      16
#define DH      64
#define BH      (NB*NH)
#define P_ELEMS ((size_t)BH*TGT*SRC)

#define MQ (NB*TGT)     // 2048
#define MK (NB*SRC)     // 4096

// bf16 hi/lo decompositions of inputs
__device__ __nv_bfloat16 g_sh[MQ*D_DIM], g_sl[MQ*D_DIM];
__device__ __nv_bfloat16 g_kh[MK*D_DIM], g_kl[MK*D_DIM];
__device__ __nv_bfloat16 g_qwh[D_DIM*D_DIM], g_qwl[D_DIM*D_DIM];
__device__ __nv_bfloat16 g_kwh[D_DIM*D_DIM], g_kwl[D_DIM*D_DIM];
// bf16 hi/lo activations (projection outputs)
__device__ __nv_bfloat16 g_aqh[MQ*D_DIM], g_aql[MQ*D_DIM];
__device__ __nv_bfloat16 g_akh[MK*D_DIM], g_akl[MK*D_DIM];

__device__ __forceinline__ void mma16816(float4& d,
    uint32_t a0, uint32_t a1, uint32_t a2, uint32_t a3,
    uint32_t b0, uint32_t b1)
{
    asm volatile(
        "mma.sync.aligned.m16n8k16.row.col.f32.bf16.bf16.f32 "
        "{%0,%1,%2,%3}, {%4,%5,%6,%7}, {%8,%9}, {%0,%1,%2,%3};"
        : "+f"(d.x), "+f"(d.y), "+f"(d.z), "+f"(d.w)
        : "r"(a0), "r"(a1), "r"(a2), "r"(a3), "r"(b0), "r"(b1));
}

__device__ __forceinline__ void ldm_x4(uint32_t& r0, uint32_t& r1,
                                       uint32_t& r2, uint32_t& r3, uint32_t addr)
{
    asm volatile("ldmatrix.sync.aligned.m8n8.x4.shared.b16 {%0,%1,%2,%3}, [%4];"
                 : "=r"(r0), "=r"(r1), "=r"(r2), "=r"(r3) : "r"(addr));
}

__device__ __forceinline__ void cp_async16(uint32_t smem_dst, const void* gsrc) {
    asm volatile("cp.async.ca.shared.global [%0], [%1], 16;" :: "r"(smem_dst), "l"(gsrc));
}
__device__ __forceinline__ void cp_async16_cg(uint32_t smem_dst, const void* gsrc) {
    asm volatile("cp.async.cg.shared.global [%0], [%1], 16;" :: "r"(smem_dst), "l"(gsrc));
}
__device__ __forceinline__ void cp_async_commit() {
    asm volatile("cp.async.commit_group;" ::: "memory");
}
__device__ __forceinline__ void cp_async_wait0() {
    asm volatile("cp.async.wait_group 0;" ::: "memory");
}
__device__ __forceinline__ uint32_t smem_u32(const void* p) {
    uint32_t a;
    asm("{ .reg .u64 t; cvta.to.shared.u64 t, %1; cvt.u32.u64 %0, t; }" : "=r"(a) : "l"(p));
    return a;
}

// ---------------------------------------------------------------------------
// Fused fp32 -> (hi, lo) bf16 decomposition for all 4 inputs (one launch).
// ---------------------------------------------------------------------------
#define N4_S  (MQ*D_DIM/4)           // 524288
#define N4_K  (MK*D_DIM/4)           // 1048576
#define N4_W  (D_DIM*D_DIM/4)        // 262144
#define CVT_BLOCKS ((N4_S + N4_K + 2*N4_W)/256)

__global__ __launch_bounds__(256)
void cvt_all(const float4* __restrict__ s,  const float4* __restrict__ k,
             const float4* __restrict__ qw, const float4* __restrict__ kw,
             ushort4* __restrict__ sh,  ushort4* __restrict__ sl,
             ushort4* __restrict__ kh,  ushort4* __restrict__ kl,
             ushort4* __restrict__ qwh, ushort4* __restrict__ qwl,
             ushort4* __restrict__ kwh, ushort4* __restrict__ kwl)
{
    int b = blockIdx.x;
    const float4* in; ushort4 *hi, *lo; int idx;
    if (b < N4_S/256) {
        in = s; hi = sh; lo = sl; idx = b * 256 + threadIdx.x;
    } else if (b < (N4_S + N4_K)/256) {
        in = k; hi = kh; lo = kl; idx = (b - N4_S/256) * 256 + threadIdx.x;
    } else if (b < (N4_S + N4_K + N4_W)/256) {
        in = qw; hi = qwh; lo = qwl; idx = (b - (N4_S + N4_K)/256) * 256 + threadIdx.x;
    } else {
        in = kw; hi = kwh; lo = kwl; idx = (b - (N4_S + N4_K + N4_W)/256) * 256 + threadIdx.x;
    }
    float4 v = in[idx];
    ushort4 h, l;
    {
        __nv_bfloat16 hb = __float2bfloat16(v.x);
        __nv_bfloat16 lb = __float2bfloat16(v.x - __bfloat162float(hb));
        h.x = *(unsigned short*)&hb; l.x = *(unsigned short*)&lb;
    }
    {
        __nv_bfloat16 hb = __float2bfloat16(v.y);
        __nv_bfloat16 lb = __float2bfloat16(v.y - __bfloat162float(hb));
        h.y = *(unsigned short*)&hb; l.y = *(unsigned short*)&lb;
    }
    {
        __nv_bfloat16 hb = __float2bfloat16(v.z);
        __nv_bfloat16 lb = __float2bfloat16(v.z - __bfloat162float(hb));
        h.z = *(unsigned short*)&hb; l.z = *(unsigned short*)&lb;
    }
    {
        __nv_bfloat16 hb = __float2bfloat16(v.w);
        __nv_bfloat16 lb = __float2bfloat16(v.w - __bfloat162float(hb));
        h.w = *(unsigned short*)&hb; l.w = *(unsigned short*)&lb;
    }
    hi[idx] = h; lo[idx] = l;
}

// ---------------------------------------------------------------------------
// mma.sync bf16-split projection GEMM + bias + ReLU -> bf16 hi/lo activations.
// CTA tile 128x128, 8 warps (4M x 2N). K chunk 32, cp.async x2, ldmatrix frags.
// TERM-MAJOR inner loop: all Ah*Wh (16 indep acc), all Al*Wh, then all Ah*Wl —
// accumulator reuse distance 16 (was 1) to hide HMMA latency.
// ---------------------------------------------------------------------------
#define CK      32
#define NCH     (D_DIM/CK)
#define STR     40
#define TILE_BYTES (128*STR*2)
#define BUF_BYTES  (4*TILE_BYTES)
#define PROJ_SMEM  (2*BUF_BYTES)     // 81920; x2 CTAs = 160KB <= 228KB

__global__ __launch_bounds__(256, 2)
void proj_mma(const float* __restrict__ q_b, const float* __restrict__ k_b)
{
    extern __shared__ char smem[];
    const int tid  = threadIdx.x;
    const int wid  = tid >> 5;
    const int lane = tid & 31;
    const int g    = lane >> 2;
    const int t    = lane & 3;
    const int warpM = wid & 3;
    const int warpN = wid >> 2;

    const int by  = blockIdx.y;
    const bool isq = by < 16;
    const int bm  = (isq ? by : by - 16) * 128;
    const int bn  = blockIdx.x * 128;

    const __nv_bfloat16* Ah = isq ? g_sh  : g_kh;
    const __nv_bfloat16* Al = isq ? g_sl  : g_kl;
    const __nv_bfloat16* Wh = isq ? g_qwh : g_kwh;
    const __nv_bfloat16* Wl = isq ? g_qwl : g_kwl;
    const float*       bias = isq ? q_b   : k_b;
    __nv_bfloat16*       CH = isq ? g_aqh : g_akh;
    __nv_bfloat16*       CL = isq ? g_aql : g_akl;

    float4 acc[2][8];
#pragma unroll
    for (int i = 0; i < 2; i++)
#pragma unroll
        for (int j = 0; j < 8; j++) acc[i][j] = make_float4(0.f, 0.f, 0.f, 0.f);

    const uint32_t smem_base = smem_u32(smem);

    const int aRow    = lane & 15;
    const int aColOff = (lane >> 4) * 8;
    const int wRowOff = (lane & 7) + ((lane >> 4) & 1) * 8;
    const int wColOff = ((lane >> 3) & 1) * 8;

    auto load_chunk = [&](int c, int buf) {
        const int k0 = c * CK;
        const uint32_t sb = smem_base + buf * BUF_BYTES;
#pragma unroll
        for (int h = 0; h < 2; h++) {
            int seg = tid + h * 256;
            int row = seg >> 2;
            int s4  = seg & 3;
            uint32_t soff = (uint32_t)(row * STR + s4 * 8) * 2;
            size_t ga = (size_t)(bm + row) * D_DIM + k0 + s4 * 8;
            size_t gw = (size_t)(bn + row) * D_DIM + k0 + s4 * 8;
            cp_async16(sb + soff,                Ah + ga);
            cp_async16(sb + TILE_BYTES   + soff, Al + ga);
            cp_async16(sb + 2*TILE_BYTES + soff, Wh + gw);
            cp_async16(sb + 3*TILE_BYTES + soff, Wl + gw);
        }
        cp_async_commit();
    };

    load_chunk(0, 0);
    cp_async_wait0();
    __syncthreads();

    for (int c = 0; c < NCH; c++) {
        const int buf = c & 1;
        if (c + 1 < NCH) load_chunk(c + 1, buf ^ 1);

        const uint32_t sbAh = smem_base + buf * BUF_BYTES;
        const uint32_t sbAl = sbAh + TILE_BYTES;
        const uint32_t sbWh = sbAh + 2*TILE_BYTES;
        const uint32_t sbWl = sbAh + 3*TILE_BYTES;

        uint32_t aH0 = sbAh + (uint32_t)((warpM*32 +      aRow) * STR + aColOff) * 2;
        uint32_t aH1 = sbAh + (uint32_t)((warpM*32 + 16 + aRow) * STR + aColOff) * 2;
        uint32_t aL0 = sbAl + (uint32_t)((warpM*32 +      aRow) * STR + aColOff) * 2;
        uint32_t aL1 = sbAl + (uint32_t)((warpM*32 + 16 + aRow) * STR + aColOff) * 2;
        uint32_t wH  = sbWh + (uint32_t)((warpN*64 + wRowOff) * STR + wColOff) * 2;
        uint32_t wL  = sbWl + (uint32_t)((warpN*64 + wRowOff) * STR + wColOff) * 2;

#pragma unroll
        for (int ks = 0; ks < CK; ks += 16) {
            const uint32_t kso = (uint32_t)ks * 2;

            // A-hi fragments + all W-hi fragments (8 j-groups, 4 ldm_x4)
            uint32_t ah[2][4];
            ldm_x4(ah[0][0], ah[0][1], ah[0][2], ah[0][3], aH0 + kso);
            ldm_x4(ah[1][0], ah[1][1], ah[1][2], ah[1][3], aH1 + kso);
            uint32_t wf[4][4];
#pragma unroll
            for (int q = 0; q < 4; q++)
                ldm_x4(wf[q][0], wf[q][1], wf[q][2], wf[q][3],
                       wH + (uint32_t)(q * 16 * STR) * 2 + kso);

            // term 1: Ah*Wh — 16 independent accumulators
#pragma unroll
            for (int q = 0; q < 4; q++)
#pragma unroll
                for (int i = 0; i < 2; i++) {
                    mma16816(acc[i][2*q],   ah[i][0], ah[i][1], ah[i][2], ah[i][3], wf[q][0], wf[q][1]);
                    mma16816(acc[i][2*q+1], ah[i][0], ah[i][1], ah[i][2], ah[i][3], wf[q][2], wf[q][3]);
                }

            // A-lo fragments; term 2: Al*Wh
            uint32_t al[2][4];
            ldm_x4(al[0][0], al[0][1], al[0][2], al[0][3], aL0 + kso);
            ldm_x4(al[1][0], al[1][1], al[1][2], al[1][3], aL1 + kso);
#pragma unroll
            for (int q = 0; q < 4; q++)
#pragma unroll
                for (int i = 0; i < 2; i++) {
                    mma16816(acc[i][2*q],   al[i][0], al[i][1], al[i][2], al[i][3], wf[q][0], wf[q][1]);
                    mma16816(acc[i][2*q+1], al[i][0], al[i][1], al[i][2], al[i][3], wf[q][2], wf[q][3]);
                }

            // W-lo fragments overwrite wf; term 3: Ah*Wl
#pragma unroll
            for (int q = 0; q < 4; q++)
                ldm_x4(wf[q][0], wf[q][1], wf[q][2], wf[q][3],
                       wL + (uint32_t)(q * 16 * STR) * 2 + kso);
#pragma unroll
            for (int q = 0; q < 4; q++)
#pragma unroll
                for (int i = 0; i < 2; i++) {
                    mma16816(acc[i][2*q],   ah[i][0], ah[i][1], ah[i][2], ah[i][3], wf[q][0], wf[q][1]);
                    mma16816(acc[i][2*q+1], ah[i][0], ah[i][1], ah[i][2], ah[i][3], wf[q][2], wf[q][3]);
                }
        }

        cp_async_wait0();
        __syncthreads();
    }

#pragma unroll
    for (int i = 0; i < 2; i++) {
        int row0 = bm + warpM * 32 + i * 16 + g;
#pragma unroll
        for (int j = 0; j < 8; j++) {
            int col = bn + warpN * 64 + j * 8 + 2 * t;
            float b0 = bias[col], b1 = bias[col + 1];
            float v[4];
            v[0] = fmaxf(acc[i][j].x + b0, 0.f);
            v[1] = fmaxf(acc[i][j].y + b1, 0.f);
            v[2] = fmaxf(acc[i][j].z + b0, 0.f);
            v[3] = fmaxf(acc[i][j].w + b1, 0.f);
            __nv_bfloat16 h[4], l[4];
#pragma unroll
            for (int u = 0; u < 4; u++) {
                h[u] = __float2bfloat16(v[u]);
                l[u] = __float2bfloat16(v[u] - __bfloat162float(h[u]));
            }
            __nv_bfloat162 h01; h01.x = h[0]; h01.y = h[1];
            __nv_bfloat162 h23; h23.x = h[2]; h23.y = h[3];
            __nv_bfloat162 l01; l01.x = l[0]; l01.y = l[1];
            __nv_bfloat162 l23; l23.x = l[2]; l23.y = l[3];
            *(__nv_bfloat162*)(CH + (size_t)row0 * D_DIM + col)       = h01;
            *(__nv_bfloat162*)(CH + (size_t)(row0 + 8) * D_DIM + col) = h23;
            *(__nv_bfloat162*)(CL + (size_t)row0 * D_DIM + col)       = l01;
            *(__nv_bfloat162*)(CL + (size_t)(row0 + 8) * D_DIM + col) = l23;
        }
    }
}

// ---------------------------------------------------------------------------
// mma.sync bf16-split energy + sigmoid (unchanged — known-passing).
// ---------------------------------------------------------------------------
#define ESTR    72
#define ETILE_BYTES (128*ESTR*2)
#define E_SMEM  (4*ETILE_BYTES)

__global__ __launch_bounds__(256)
void energy_mma(const float* __restrict__ ebias, float* __restrict__ P)
{
    extern __shared__ char smem[];
    const int tid  = threadIdx.x;
    const int wid  = tid >> 5;
    const int lane = tid & 31;
    const int g    = lane >> 2;
    const int t    = lane & 3;
    const int warpM = wid & 3;
    const int warpN = wid >> 2;

    const int bh = blockIdx.z;
    const int bb = bh >> 4;
    const int hh = bh & 15;
    const int m0 = blockIdx.y * 128;
    const int n0 = blockIdx.x * 128;

    const __nv_bfloat16* Qh = g_aqh + (size_t)bb * TGT * D_DIM + hh * DH;
    const __nv_bfloat16* Ql = g_aql + (size_t)bb * TGT * D_DIM + hh * DH;
    const __nv_bfloat16* Kh = g_akh + (size_t)bb * SRC * D_DIM + hh * DH;
    const __nv_bfloat16* Kl = g_akl + (size_t)bb * SRC * D_DIM + hh * DH;

    const uint32_t sb = smem_u32(smem);

#pragma unroll
    for (int h = 0; h < 4; h++) {
        int seg = tid + h * 256;
        int row = seg >> 3;
        int s   = seg & 7;
        uint32_t soff = (uint32_t)(row * ESTR + s * 8) * 2;
        cp_async16(sb + soff,                 Qh + (size_t)(m0 + row) * D_DIM + s * 8);
        cp_async16(sb + ETILE_BYTES   + soff, Ql + (size_t)(m0 + row) * D_DIM + s * 8);
        cp_async16(sb + 2*ETILE_BYTES + soff, Kh + (size_t)(n0 + row) * D_DIM + s * 8);
        cp_async16(sb + 3*ETILE_BYTES + soff, Kl + (size_t)(n0 + row) * D_DIM + s * 8);
    }
    cp_async_commit();
    cp_async_wait0();
    __syncthreads();

    const __nv_bfloat16* sQh = (const __nv_bfloat16*)smem;
    const __nv_bfloat16* sQl = (const __nv_bfloat16*)(smem + ETILE_BYTES);
    const __nv_bfloat16* sKh = (const __nv_bfloat16*)(smem + 2*ETILE_BYTES);
    const __nv_bfloat16* sKl = (const __nv_bfloat16*)(smem + 3*ETILE_BYTES);

    float4 acc[2][8];
#pragma unroll
    for (int i = 0; i < 2; i++)
#pragma unroll
        for (int j = 0; j < 8; j++) acc[i][j] = make_float4(0.f, 0.f, 0.f, 0.f);

#pragma unroll
    for (int ks = 0; ks < DH; ks += 16) {
        uint32_t ah[2][4], al[2][4];
#pragma unroll
        for (int i = 0; i < 2; i++) {
            int r0 = warpM * 32 + i * 16 + g;
            const __nv_bfloat16* p0 = sQh + r0 * ESTR + ks + 2 * t;
            const __nv_bfloat16* p1 = sQh + (r0 + 8) * ESTR + ks + 2 * t;
            ah[i][0] = *(const uint32_t*)p0;
            ah[i][1] = *(const uint32_t*)p1;
            ah[i][2] = *(const uint32_t*)(p0 + 8);
            ah[i][3] = *(const uint32_t*)(p1 + 8);
            const __nv_bfloat16* q0 = sQl + r0 * ESTR + ks + 2 * t;
            const __nv_bfloat16* q1 = sQl + (r0 + 8) * ESTR + ks + 2 * t;
            al[i][0] = *(const uint32_t*)q0;
            al[i][1] = *(const uint32_t*)q1;
            al[i][2] = *(const uint32_t*)(q0 + 8);
            al[i][3] = *(const uint32_t*)(q1 + 8);
        }
#pragma unroll
        for (int j = 0; j < 8; j++) {
            int rw = warpN * 64 + j * 8 + g;
            const __nv_bfloat16* pw = sKh + rw * ESTR + ks + 2 * t;
            uint32_t bh0 = *(const uint32_t*)pw;
            uint32_t bh1 = *(const uint32_t*)(pw + 8);
            const __nv_bfloat16* pl = sKl + rw * ESTR + ks + 2 * t;
            uint32_t bl0 = *(const uint32_t*)pl;
            uint32_t bl1 = *(const uint32_t*)(pl + 8);
#pragma unroll
            for (int i = 0; i < 2; i++) {
                mma16816(acc[i][j], ah[i][0], ah[i][1], ah[i][2], ah[i][3], bh0, bh1);
                mma16816(acc[i][j], ah[i][0], ah[i][1], ah[i][2], ah[i][3], bl0, bl1);
                mma16816(acc[i][j], al[i][0], al[i][1], al[i][2], al[i][3], bh0, bh1);
            }
        }
    }

    const float eb5 = ebias[0] * 5.0f;

#pragma unroll
    for (int i = 0; i < 2; i++) {
        int row0 = m0 + warpM * 32 + i * 16 + g;
#pragma unroll
        for (int j = 0; j < 8; j++) {
            int col = n0 + warpN * 64 + j * 8 + 2 * t;
            float z0 = fmaf(acc[i][j].x, 0.625f, eb5);
            float z1 = fmaf(acc[i][j].y, 0.625f, eb5);
            float z2 = fmaf(acc[i][j].z, 0.625f, eb5);
            float z3 = fmaf(acc[i][j].w, 0.625f, eb5);
            float2 o0, o1;
            o0.x = 1.0f / (1.0f + __expf(-z0));
            o0.y = 1.0f / (1.0f + __expf(-z1));
            o1.x = 1.0f / (1.0f + __expf(-z2));
            o1.y = 1.0f / (1.0f + __expf(-z3));
            float* dst0 = P + ((size_t)bh * TGT + row0) * SRC + col;
            float* dst1 = P + ((size_t)bh * TGT + row0 + 8) * SRC + col;
            *(float2*)dst0 = o0;
            *(float2*)dst1 = o1;
        }
    }
}

// ---------------------------------------------------------------------------
// Monotonic alignment v6 (unchanged — measured 63us).
// ---------------------------------------------------------------------------
__global__ __launch_bounds__(32)
void alpha_kernel(const float* __restrict__ p, float* __restrict__ alpha)
{
    __shared__ float4 srow[8 * 128];
    const int lane = threadIdx.x;
    const int bh   = blockIdx.x;

    const float* pg = p + (size_t)bh * TGT * SRC;
    float4*      ar = (float4*)(alpha + (size_t)bh * TGT * SRC + lane * 16);
    const uint32_t sbase = smem_u32(srow);

    auto issue_row = [&](int r) {
        int rc = (r < TGT) ? r : (TGT - 1);
        uint32_t slot = (uint32_t)(r & 7);
        const float* src = pg + (size_t)rc * SRC + lane * 16;
#pragma unroll
        for (int c = 0; c < 4; c++)
            cp_async16_cg(sbase + slot * 2048 + (uint32_t)(c * 32 + lane) * 16,
                          src + c * 4);
        cp_async_commit();
    };

#pragma unroll
    for (int r = 0; r < 7; r++) issue_row(r);
    asm volatile("cp.async.wait_group 6;" ::: "memory");

    float Bv[16];
#pragma unroll
    for (int j = 0; j < 16; j++) Bv[j] = 0.f;
    if (lane == 0) Bv[0] = 1.f;

    float pc[16], Av[16], PaL[8], PaH[8];
    float k1, k2, k4, k8, k16;

    auto prep = [&](float4 f0, float4 f1, float4 f2, float4 f3) {
        pc[0]=f0.x;  pc[1]=f0.y;  pc[2]=f0.z;  pc[3]=f0.w;
        pc[4]=f1.x;  pc[5]=f1.y;  pc[6]=f1.z;  pc[7]=f1.w;
        pc[8]=f2.x;  pc[9]=f2.y;  pc[10]=f2.z; pc[11]=f2.w;
        pc[12]=f3.x; pc[13]=f3.y; pc[14]=f3.z; pc[15]=f3.w;
        float prevlast = __shfl_up_sync(0xffffffffu, pc[15], 1);
        Av[0] = (lane == 0) ? 0.f : (1.f - prevlast);
#pragma unroll
        for (int j = 1; j < 16; j++) Av[j] = 1.f - pc[j-1];
        PaL[0] = Av[0];
#pragma unroll
        for (int j = 1; j < 8; j++) PaL[j] = PaL[j-1] * Av[j];
        PaH[0] = Av[8];
#pragma unroll
        for (int j = 1; j < 8; j++) PaH[j] = PaH[j-1] * Av[8+j];
        float m = PaL[7] * PaH[7], s;
        k1  = (lane >= 1)  ? m : 0.f;
        s = __shfl_up_sync(0xffffffffu, m, 1);  m *= s;
        k2  = (lane >= 2)  ? m : 0.f;
        s = __shfl_up_sync(0xffffffffu, m, 2);  m *= s;
        k4  = (lane >= 4)  ? m : 0.f;
        s = __shfl_up_sync(0xffffffffu, m, 4);  m *= s;
        k8  = (lane >= 8)  ? m : 0.f;
        s = __shfl_up_sync(0xffffffffu, m, 8);  m *= s;
        k16 = (lane >= 16) ? m : 0.f;
    };

    {
        const float4* base = srow + 0 * 128 + lane;
        prep(base[0], base[32], base[64], base[96]);
    }

    for (int i = 0; i < TGT; i++) {
        issue_row(i + 7);
        asm volatile("cp.async.wait_group 6;" ::: "memory");

        const float4* nbase = srow + (uint32_t)((i + 1) & 7) * 128 + lane;
        float4 nf0 = nbase[0];
        float4 nf1 = nbase[32];
        float4 nf2 = nbase[64];
        float4 nf3 = nbase[96];

        float Pl[8], Ph[8];
        Pl[0] = Bv[0];
#pragma unroll
        for (int j = 1; j < 8; j++) Pl[j] = fmaf(Pl[j-1], Av[j], Bv[j]);
        Ph[0] = Bv[8];
#pragma unroll
        for (int j = 1; j < 8; j++) Ph[j] = fmaf(Ph[j-1], Av[8+j], Bv[8+j]);

        float b = fmaf(Pl[7], PaH[7], Ph[7]);

        float s;
        s = __shfl_up_sync(0xffffffffu, b, 1);  b = fmaf(s, k1,  b);
        s = __shfl_up_sync(0xffffffffu, b, 2);  b = fmaf(s, k2,  b);
        s = __shfl_up_sync(0xffffffffu, b, 4);  b = fmaf(s, k4,  b);
        s = __shfl_up_sync(0xffffffffu, b, 8);  b = fmaf(s, k8,  b);
        s = __shfl_up_sync(0xffffffffu, b, 16); b = fmaf(s, k16, b);

        float qin = __shfl_up_sync(0xffffffffu, b, 1);
        qin = (lane == 0) ? 0.f : qin;
        float qmid = fmaf(qin, PaL[7], Pl[7]);

#pragma unroll
        for (int j = 0; j < 8; j++)
            Bv[j] = pc[j] * fmaf(qin, PaL[j], Pl[j]);
#pragma unroll
        for (int j = 0; j < 8; j++)
            Bv[8+j] = pc[8+j] * fmaf(qmid, PaH[j], Ph[j]);

        __stcs(ar + (size_t)i * 128 + 0, make_float4(Bv[0],  Bv[1],  Bv[2],  Bv[3]));
        __stcs(ar + (size_t)i * 128 + 1, make_float4(Bv[4],  Bv[5],  Bv[6],  Bv[7]));
        __stcs(ar + (size_t)i * 128 + 2, make_float4(Bv[8],  Bv[9],  Bv[10], Bv[11]));
        __stcs(ar + (size_t)i * 128 + 3, make_float4(Bv[12], Bv[13], Bv[14], Bv[15]));

        prep(nf0, nf1, nf2, nf3);
    }
}

// ---------------------------------------------------------------------------
extern "C" void kernel_launch(void* const* d_in, const int* in_sizes, int n_in,
                              void* d_out, int out_size)
{
    const float* seqs  = (const float*)d_in[0];
    const float* keys  = (const float*)d_in[1];
    const float* q_w   = (const float*)d_in[2];
    const float* q_b   = (const float*)d_in[3];
    const float* k_w   = (const float*)d_in[4];
    const float* k_b   = (const float*)d_in[5];
    const float* ebias = (const float*)d_in[6];

    float* p_out = (float*)d_out;
    float* a_out = p_out + P_ELEMS;

    void *sh, *sl, *kh, *kl, *qwh, *qwl, *kwh, *kwl;
    cudaGetSymbolAddress(&sh,  g_sh);  cudaGetSymbolAddress(&sl,  g_sl);
    cudaGetSymbolAddress(&kh,  g_kh);  cudaGetSymbolAddress(&kl,  g_kl);
    cudaGetSymbolAddress(&qwh, g_qwh); cudaGetSymbolAddress(&qwl, g_qwl);
    cudaGetSymbolAddress(&kwh, g_kwh); cudaGetSymbolAddress(&kwl, g_kwl);

    cudaFuncSetAttribute(proj_mma,   cudaFuncAttributeMaxDynamicSharedMemorySize, PROJ_SMEM);
    cudaFuncSetAttribute(energy_mma, cudaFuncAttributeMaxDynamicSharedMemorySize, E_SMEM);

    cvt_all<<<CVT_BLOCKS, 256>>>((const float4*)seqs, (const float4*)keys,
                                 (const float4*)q_w, (const float4*)k_w,
                                 (ushort4*)sh, (ushort4*)sl, (ushort4*)kh, (ushort4*)kl,
                                 (ushort4*)qwh, (ushort4*)qwl, (ushort4*)kwh, (ushort4*)kwl);

    proj_mma<<<dim3(8, 48), 256, PROJ_SMEM>>>(q_b, k_b);
    energy_mma<<<dim3(4, 2, BH), 256, E_SMEM>>>(ebias, p_out);
    alpha_kernel<<<BH, 32>>>(p_out, a_out);
}